// round 15
// baseline (speedup 1.0000x reference)
#include <cuda_runtime.h>
#include <cuda_bf16.h>
#include <cstdint>
#include <math.h>

// ---------------- problem constants ----------------
#define BB 4
#define HH 480
#define WW 640
#define HWW (HH*WW)
#define BHW (BB*HWW)
#define RAD 4
#define THR 0.005f
#define MAXKP 1024
#define CAP 16384
#define NBUCK 4096
#define SELCAP 2048
#define CKCAP 12288
#define KTOT 704

#define C1 64
#define H1 240
#define W1 320
#define C2 128
#define H2 120
#define W2 160
#define C3 256
#define H3 60
#define W3 80
#define C4 256
#define H4 30
#define W4 40

// NMS tiles
#define TX 64
#define TY 16

// ---------------- scratch ----------------
__device__ unsigned char      g_maxmask[BHW];
__device__ unsigned long long g_cand[BB*CAP];
__device__ int                g_count[BB];
__device__ int                g_hist[BB*NBUCK];
__device__ int                g_selidx[BB*MAXKP];
__device__ int                g_sporder[BB*MAXKP];   // spatial-order -> rank
__device__ __align__(16) __nv_bfloat16 g_Xh[(size_t)BB*MAXKP*KTOT];
__device__ __align__(16) __nv_bfloat16 g_Xl[(size_t)BB*MAXKP*KTOT];
__device__ __align__(16) __nv_bfloat16 g_Mh[256*KTOT];
__device__ __align__(16) __nv_bfloat16 g_Ml[256*KTOT];
__device__ float              g_bias[256];

// ---------------- fused NMS A (+ reset/fold layer at blockIdx.z==4) ----------------
__global__ void __launch_bounds__(256) k_nmsA(const float* __restrict__ sc,
    const float* __restrict__ mw,
    const float* __restrict__ l0w, const float* __restrict__ l1w,
    const float* __restrict__ l2w,
    const float* __restrict__ mb,
    const float* __restrict__ l0b, const float* __restrict__ l1b,
    const float* __restrict__ l2b)
{
    int tid = threadIdx.x;

    if (blockIdx.z == 4) {
        int bid = blockIdx.y*10 + blockIdx.x;            // 0..299
        if (bid < 64) {
            g_hist[bid*256 + tid] = 0;
            if (bid == 0 && tid < BB) g_count[tid] = 0;
        }
        if (bid == 0) {
            int o = tid;
            const float* mrow = mw + o*KTOT;
            float acc = mb[o];
            for (int j = 0; j < 64;  j++) acc += mrow[j]       * l2b[j];
            for (int j = 0; j < 128; j++) acc += mrow[64 + j]  * l1b[j];
            for (int j = 0; j < 256; j++) acc += mrow[448 + j] * l0b[j];
            g_bias[o] = acc;
        }
        int gid = bid*256 + tid;
        for (int t = gid; t < 256*KTOT; t += 300*256) {
            int o = t / KTOT, i = t % KTOT;
            const float* mrow = mw + o*KTOT;
            float acc = 0.f;
            if (i < 64) {
                for (int j = 0; j < 64; j++)  acc += mrow[j]       * l2w[j*64  + i];
            } else if (i < 192) {
                int ii = i - 64;
                for (int j = 0; j < 128; j++) acc += mrow[64 + j]  * l1w[j*128 + ii];
            } else if (i < 448) {
                acc = mrow[i];
            } else {
                int ii = i - 448;
                for (int j = 0; j < 256; j++) acc += mrow[448 + j] * l0w[j*256 + ii];
            }
            __nv_bfloat16 hi = __float2bfloat16(acc);
            g_Mh[t] = hi;
            g_Ml[t] = __float2bfloat16(acc - __bfloat162float(hi));
        }
        return;
    }

    __shared__ float         s0[40][89];
    __shared__ float         h1[40][81];
    __shared__ unsigned char m0[32][84];
    __shared__ unsigned char hor1[32][76];
    __shared__ unsigned char sup[24][76];
    __shared__ float         ss1[24][76];
    __shared__ float         h2[24][68];

    int b = blockIdx.z;
    int x0 = blockIdx.x*TX, y0 = blockIdx.y*TY;
    const float* S = sc + b*HWW;
    int tx = tid & 63, ty = tid >> 6;

    for (int ly = ty; ly < 40; ly += 4) {
        #pragma unroll
        for (int lxb = 0; lxb < 2; lxb++) {
            int lx = lxb*64 + tx;
            if (lx < 88) {
                int gx = x0 + lx - 12, gy = y0 + ly - 12;
                s0[ly][lx] = (gx >= 0 && gx < WW && gy >= 0 && gy < HH)
                           ? S[gy*WW + gx] : -INFINITY;
            }
        }
    }
    __syncthreads();
    for (int ly = ty; ly < 40; ly += 4) {
        #pragma unroll
        for (int lxb = 0; lxb < 2; lxb++) {
            int lx = lxb*64 + tx;
            if (lx < 80) {
                float m = s0[ly][lx];
                #pragma unroll
                for (int d = 1; d < 9; d++) m = fmaxf(m, s0[ly][lx+d]);
                h1[ly][lx] = m;
            }
        }
    }
    __syncthreads();
    for (int ly = ty; ly < 32; ly += 4) {
        #pragma unroll
        for (int lxb = 0; lxb < 2; lxb++) {
            int lx = lxb*64 + tx;
            if (lx < 80) {
                float m = h1[ly][lx];
                #pragma unroll
                for (int d = 1; d < 9; d++) m = fmaxf(m, h1[ly+d][lx]);
                int gx = x0 + lx - 8, gy = y0 + ly - 8;
                bool in = (gx >= 0 && gx < WW && gy >= 0 && gy < HH);
                m0[ly][lx] = (in && s0[ly+4][lx+4] == m) ? 1 : 0;
            }
        }
    }
    __syncthreads();
    for (int ly = ty; ly < 32; ly += 4) {
        #pragma unroll
        for (int lxb = 0; lxb < 2; lxb++) {
            int lx = lxb*64 + tx;
            if (lx < 72) {
                unsigned char u = m0[ly][lx];
                #pragma unroll
                for (int d = 1; d < 9; d++) u |= m0[ly][lx+d];
                hor1[ly][lx] = u;
            }
        }
    }
    __syncthreads();
    for (int ly = ty; ly < 24; ly += 4) {
        #pragma unroll
        for (int lxb = 0; lxb < 2; lxb++) {
            int lx = lxb*64 + tx;
            if (lx < 72) {
                unsigned char u = hor1[ly][lx];
                #pragma unroll
                for (int d = 1; d < 9; d++) u |= hor1[ly+d][lx];
                sup[ly][lx] = u;
                int gx = x0 + lx - 4, gy = y0 + ly - 4;
                float v = -INFINITY;
                if (gx >= 0 && gx < WW && gy >= 0 && gy < HH)
                    v = u ? 0.0f : s0[ly+8][lx+8];
                ss1[ly][lx] = v;
            }
        }
    }
    __syncthreads();
    for (int ly = ty; ly < 24; ly += 4) {
        int lx = tx;
        float m = ss1[ly][lx];
        #pragma unroll
        for (int d = 1; d < 9; d++) m = fmaxf(m, ss1[ly][lx+d]);
        h2[ly][lx] = m;
    }
    __syncthreads();
    for (int ly = ty; ly < 16; ly += 4) {
        int lx = tx;
        float m = h2[ly][lx];
        #pragma unroll
        for (int d = 1; d < 9; d++) m = fmaxf(m, h2[ly+d][lx]);
        unsigned char sp = sup[ly+4][lx+4];
        float ssc = ss1[ly+4][lx+4];
        unsigned char newm = ((ssc == m) && !sp) ? 1 : 0;
        int gx = x0 + lx, gy = y0 + ly;
        g_maxmask[b*HWW + gy*WW + gx] = m0[ly+8][lx+8] | newm;
    }
}

// ---------------- fused NMS B: iteration 2 + candidate emission ----------------
__global__ void __launch_bounds__(256) k_nmsB(const float* __restrict__ sc)
{
    __shared__ unsigned char mm[TY+16][TX+16+4];
    __shared__ unsigned char hor[TY+16][TX+8+4];
    __shared__ unsigned char sup[TY+8][TX+8+4];
    __shared__ float         sfl[TY+8][TX+8+4];
    __shared__ float         hmx[TY+8][TX+4];
    int b = blockIdx.z;
    int x0 = blockIdx.x*TX, y0 = blockIdx.y*TY;
    const float* S = sc + b*HWW;
    const unsigned char* SM = g_maxmask + b*HWW;

    for (int e = threadIdx.x; e < (TY+16)*(TX+16); e += 256) {
        int ly = e / (TX+16), lx = e % (TX+16);
        int gx = x0 + lx - 8, gy = y0 + ly - 8;
        unsigned char v = 0;
        if (gx >= 0 && gx < WW && gy >= 0 && gy < HH) v = SM[gy*WW + gx];
        mm[ly][lx] = v;
    }
    __syncthreads();
    for (int e = threadIdx.x; e < (TY+16)*(TX+8); e += 256) {
        int ly = e / (TX+8), lx = e % (TX+8);
        unsigned char u = mm[ly][lx];
        #pragma unroll
        for (int d = 1; d < 9; d++) u |= mm[ly][lx+d];
        hor[ly][lx] = u;
    }
    __syncthreads();
    for (int e = threadIdx.x; e < (TY+8)*(TX+8); e += 256) {
        int ly = e / (TX+8), lx = e % (TX+8);
        unsigned char u = hor[ly][lx];
        #pragma unroll
        for (int d = 1; d < 9; d++) u |= hor[ly+d][lx];
        sup[ly][lx] = u;
        int gx = x0 + lx - 4, gy = y0 + ly - 4;
        float v = -INFINITY;
        if (gx >= 0 && gx < WW && gy >= 0 && gy < HH) v = u ? 0.0f : S[gy*WW + gx];
        sfl[ly][lx] = v;
    }
    __syncthreads();
    for (int e = threadIdx.x; e < (TY+8)*TX; e += 256) {
        int ly = e / TX, lx = e % TX;
        float m = sfl[ly][lx];
        #pragma unroll
        for (int d = 1; d < 9; d++) m = fmaxf(m, sfl[ly][lx+d]);
        hmx[ly][lx] = m;
    }
    __syncthreads();
    for (int e = threadIdx.x; e < TY*TX; e += 256) {
        int ly = e / TX, lx = e % TX;
        float m = hmx[ly][lx];
        #pragma unroll
        for (int d = 1; d < 9; d++) m = fmaxf(m, hmx[ly+d][lx]);
        unsigned char sp = sup[ly+4][lx+4];
        float ss = sfl[ly+4][lx+4];
        unsigned char newm = ((ss == m) && !sp) ? 1 : 0;
        int gx = x0 + lx, gy = y0 + ly;
        unsigned char maskv = mm[ly+8][lx+8] | newm;
        if (maskv && gx >= RAD && gx < WW-RAD && gy >= RAD && gy < HH-RAD) {
            float sv = S[gy*WW + gx];
            if (sv > THR) {
                unsigned sb = __float_as_uint(sv);
                int local = gy*WW + gx;
                int p = atomicAdd(&g_count[b], 1);
                if (p < CAP)
                    g_cand[b*CAP + p] = (((unsigned long long)sb) << 32)
                                      | (unsigned long long)(0xFFFFFFFFu - (unsigned)local);
                atomicAdd(&g_hist[b*NBUCK + (sb >> 20)], 1);
            }
        }
    }
}

// ---------------- warp-shuffle suffix scan over 1024 threads ----------------
__device__ __forceinline__ int suffix_scan1024(int v, int tid, int* warptot)
{
    int lane = tid & 31, wid = tid >> 5;
    int s = v;
    #pragma unroll
    for (int o = 1; o < 32; o <<= 1) {
        int t = __shfl_down_sync(0xFFFFFFFFu, s, o);
        if (lane + o < 32) s += t;
    }
    if (lane == 0) warptot[wid] = s;
    __syncthreads();
    if (wid == 0) {
        int wv = warptot[lane];
        int ws = wv;
        #pragma unroll
        for (int o = 1; o < 32; o <<= 1) {
            int t = __shfl_down_sync(0xFFFFFFFFu, ws, o);
            if (lane + o < 32) ws += t;
        }
        warptot[lane] = ws - wv;
    }
    __syncthreads();
    return s + warptot[wid];
}

// ---------------- single-global-pass radix-select + rank scatter + spatial order ----------------
__global__ void __launch_bounds__(1024) k_select(float* __restrict__ outKp,
                                                 float* __restrict__ outSc)
{
    extern __shared__ unsigned long long dyns[];
    unsigned long long* ckey = dyns;
    unsigned long long* sel  = dyns + CKCAP;
    int* hist2 = (int*)(dyns + CKCAP + SELCAP);   // reused as sidx after phase 2
    __shared__ int warptot[32];
    __shared__ int s_T, s_T2, s_m, s_nhi, s_msel;

    int b = blockIdx.x;
    int tid = threadIdx.x;
    int cnt = g_count[b];
    if (cnt > CKCAP) cnt = CKCAP;

    int c0 = g_hist[b*NBUCK + tid*4 + 0];
    int c1 = g_hist[b*NBUCK + tid*4 + 1];
    int c2 = g_hist[b*NBUCK + tid*4 + 2];
    int c3 = g_hist[b*NBUCK + tid*4 + 3];
    if (tid == 0) { s_T = 0; s_T2 = 0; s_m = 0; s_nhi = 0; }
    hist2[tid] = 0; hist2[tid+1024] = 0; hist2[tid+2048] = 0; hist2[tid+3072] = 0;
    __syncthreads();
    int suf = suffix_scan1024(c0 + c1 + c2 + c3, tid, warptot);
    {
        int nx = suf - (c0 + c1 + c2 + c3);
        int C3v = nx + c3, C2v = C3v + c2, C1v = C2v + c1, C0v = C1v + c0;
        if (C0v >= MAXKP && C1v < MAXKP) s_T = tid*4 + 0;
        if (C1v >= MAXKP && C2v < MAXKP) s_T = tid*4 + 1;
        if (C2v >= MAXKP && C3v < MAXKP) s_T = tid*4 + 2;
        if (C3v >= MAXKP && nx  < MAXKP) s_T = tid*4 + 3;
    }
    __syncthreads();
    int Tstar = s_T;

    for (int t = tid; t < cnt; t += 1024) {
        unsigned long long key = g_cand[b*CAP + t];
        ckey[t] = key;
        int bucket = (int)(key >> 52);
        if (bucket > Tstar)        atomicAdd(&s_nhi, 1);
        else if (bucket == Tstar)  atomicAdd(&hist2[(int)((key >> 40) & 0xFFF)], 1);
    }
    __syncthreads();
    int q0 = hist2[tid*4 + 0], q1 = hist2[tid*4 + 1];
    int q2 = hist2[tid*4 + 2], q3 = hist2[tid*4 + 3];
    int nhi = s_nhi;
    __syncthreads();
    int suf2 = suffix_scan1024(q0 + q1 + q2 + q3, tid, warptot);
    {
        int nx = suf2 - (q0 + q1 + q2 + q3);
        int D3 = nx + q3, D2 = D3 + q2, D1 = D2 + q1, D0 = D1 + q0;
        if (nhi + D0 >= MAXKP && nhi + D1 < MAXKP) { s_T2 = tid*4 + 0; s_msel = nhi + D0; }
        if (nhi + D1 >= MAXKP && nhi + D2 < MAXKP) { s_T2 = tid*4 + 1; s_msel = nhi + D1; }
        if (nhi + D2 >= MAXKP && nhi + D3 < MAXKP) { s_T2 = tid*4 + 2; s_msel = nhi + D2; }
        if (nhi + D3 >= MAXKP && nhi + nx < MAXKP) { s_T2 = tid*4 + 3; s_msel = nhi + D3; }
        if (tid == 0 && nhi + suf2 < MAXKP) s_msel = nhi + suf2;
    }
    __syncthreads();
    int T2 = s_T2;

    for (int t = tid; t < cnt; t += 1024) {
        unsigned long long key = ckey[t];
        int bucket = (int)(key >> 52);
        int sub    = (int)((key >> 40) & 0xFFF);
        if (bucket > Tstar || (bucket == Tstar && sub >= T2)) {
            int p = atomicAdd(&s_m, 1);
            if (p < SELCAP) sel[p] = key;
        }
    }
    __syncthreads();
    int m = s_m; if (m > SELCAP) m = SELCAP;

    int* sidx = hist2;   // reuse: [0..MAXKP) pixel idx by rank
    for (int t = tid; t < m; t += 1024) {
        unsigned long long key = sel[t];
        int rank = 0;
        int j = 0;
        for (; j + 4 <= m; j += 4) {
            rank += (sel[j]   > key);
            rank += (sel[j+1] > key);
            rank += (sel[j+2] > key);
            rank += (sel[j+3] > key);
        }
        for (; j < m; j++) rank += (sel[j] > key);
        if (rank < MAXKP) {
            float s = __uint_as_float((unsigned)(key >> 32));
            int idx = (int)(0xFFFFFFFFu - (unsigned)(key & 0xFFFFFFFFu));
            outKp[(b*MAXKP + rank)*2 + 0] = (float)(idx % WW);
            outKp[(b*MAXKP + rank)*2 + 1] = (float)(idx / WW);
            outSc[b*MAXKP + rank] = s;
            g_selidx[b*MAXKP + rank] = idx;
            sidx[rank] = idx;
        }
    }
    for (int p = m + tid; p < MAXKP; p += 1024) {
        int idx = p - m;
        outKp[(b*MAXKP + p)*2 + 0] = (float)(idx % WW);
        outKp[(b*MAXKP + p)*2 + 1] = (float)(idx / WW);
        outSc[b*MAXKP + p] = -1.0f;
        g_selidx[b*MAXKP + p] = idx;
        sidx[p] = idx;
    }
    __syncthreads();

    // spatial ordering: sprank = #keypoints with smaller pixel idx (ties by rank).
    // pad idx < 1024 < 2564 <= real idx, so values collide only among pads (unique) .
    {
        int myidx = sidx[tid];
        int sprank = 0;
        for (int j = 0; j < MAXKP; j++) {
            int oj = sidx[j];
            sprank += (oj < myidx) || (oj == myidx && j < tid);
        }
        g_sporder[b*MAXKP + sprank] = tid;
    }
}

// ---------------- descriptor sampling: tap-major, 2 keypoints/block, spatial order ----------------
__global__ void __launch_bounds__(704) k_sample(
    const float* __restrict__ d1, const float* __restrict__ d2,
    const float* __restrict__ d3, const float* __restrict__ d4)
{
    __shared__ float xs[2][KTOT];
    __shared__ float wsum[2][22];
    __shared__ int rk[2];
    int b = blockIdx.x >> 9;                 // 512 blocks per batch
    int sp = (blockIdx.x & 511) * 2;
    int tid = threadIdx.x;
    if (tid < 2) rk[tid] = g_sporder[b*MAXKP + sp + tid];
    __syncthreads();
    int idx0 = g_selidx[b*MAXKP + rk[0]];
    int idx1 = g_selidx[b*MAXKP + rk[1]];

    const float* dptr; int h, w, sfac, warp0, nw, choff;
    if (tid < 64)       { dptr = d1 + (size_t)b*C1*H1*W1; h=H1; w=W1; sfac=2;  warp0=0;  nw=2; choff=0;   }
    else if (tid < 192) { dptr = d2 + (size_t)b*C2*H2*W2; h=H2; w=W2; sfac=4;  warp0=2;  nw=4; choff=64;  }
    else if (tid < 448) { dptr = d3 + (size_t)b*C3*H3*W3; h=H3; w=W3; sfac=8;  warp0=6;  nw=8; choff=192; }
    else                { dptr = d4 + (size_t)b*C4*H4*W4; h=H4; w=W4; sfac=16; warp0=14; nw=8; choff=448; }

    int lane = tid & 31, wid = tid >> 5;
    int tap = lane & 3, chl = lane >> 2;
    int warp_in_group = wid - warp0;

    int toff[2]; float wt[2];
    #pragma unroll
    for (int k = 0; k < 2; k++) {
        int idx = k ? idx1 : idx0;
        float kx = (float)(idx % WW), ky = (float)(idx / WW);
        float kxs = kx - (float)sfac * 0.5f + 0.5f;
        float kys = ky - (float)sfac * 0.5f + 0.5f;
        float gx = kxs / (float)(w * sfac - 1) * 2.0f - 1.0f;
        float gy = kys / (float)(h * sfac - 1) * 2.0f - 1.0f;
        float x = (gx + 1.0f) * 0.5f * (float)(w - 1);
        float y = (gy + 1.0f) * 0.5f * (float)(h - 1);
        float x0f = floorf(x), y0f = floorf(y);
        float wx1 = x - x0f, wy1 = y - y0f;
        float wx0 = 1.0f - wx1, wy0 = 1.0f - wy1;
        int x0 = (int)x0f, y0 = (int)y0f;
        int x1 = x0 + 1,  y1 = y0 + 1;
        int xc0 = min(max(x0, 0), w-1), xc1 = min(max(x1, 0), w-1);
        int yc0 = min(max(y0, 0), h-1), yc1 = min(max(y1, 0), h-1);
        float f00 = (x0 >= 0 && x0 < w && y0 >= 0 && y0 < h) ? 1.f : 0.f;
        float f10 = (x1 >= 0 && x1 < w && y0 >= 0 && y0 < h) ? 1.f : 0.f;
        float f01 = (x0 >= 0 && x0 < w && y1 >= 0 && y1 < h) ? 1.f : 0.f;
        float f11 = (x1 >= 0 && x1 < w && y1 >= 0 && y1 < h) ? 1.f : 0.f;
        float w00 = (wx0*wy0)*f00, w10 = (wx1*wy0)*f10;
        float w01 = (wx0*wy1)*f01, w11 = (wx1*wy1)*f11;
        int ytap = (tap & 2) ? yc1 : yc0;
        int xtap = (tap & 1) ? xc1 : xc0;
        wt[k]  = (tap == 0) ? w00 : (tap == 1) ? w10 : (tap == 2) ? w01 : w11;
        toff[k] = ytap*w + xtap;
    }

    #pragma unroll
    for (int i = 0; i < 4; i++) {
        int chg = warp_in_group*32 + i*8 + chl;
        const float* base = dptr + (size_t)chg*h*w;
        float v0 = __ldg(base + toff[0]) * wt[0];
        float v1 = __ldg(base + toff[1]) * wt[1];
        v0 += __shfl_xor_sync(0xFFFFFFFFu, v0, 1);
        v1 += __shfl_xor_sync(0xFFFFFFFFu, v1, 1);
        v0 += __shfl_xor_sync(0xFFFFFFFFu, v0, 2);
        v1 += __shfl_xor_sync(0xFFFFFFFFu, v1, 2);
        if (tap == 0) { xs[0][choff + chg] = v0; xs[1][choff + chg] = v1; }
    }
    __syncthreads();

    float rv0 = xs[0][tid], rv1 = xs[1][tid];
    float sq0 = rv0*rv0, sq1 = rv1*rv1;
    #pragma unroll
    for (int o = 16; o > 0; o >>= 1) {
        sq0 += __shfl_xor_sync(0xFFFFFFFFu, sq0, o);
        sq1 += __shfl_xor_sync(0xFFFFFFFFu, sq1, o);
    }
    if (lane == 0) { wsum[0][wid] = sq0; wsum[1][wid] = sq1; }
    __syncthreads();
    float tot0 = 0.f, tot1 = 0.f;
    for (int i = 0; i < nw; i++) { tot0 += wsum[0][warp0 + i]; tot1 += wsum[1][warp0 + i]; }
    float v0 = rv0 / fmaxf(sqrtf(tot0), 1e-12f);
    float v1 = rv1 / fmaxf(sqrtf(tot1), 1e-12f);
    __nv_bfloat16 h0 = __float2bfloat16(v0);
    __nv_bfloat16 h1v = __float2bfloat16(v1);
    size_t r0 = (size_t)(b*MAXKP + rk[0]) * KTOT + tid;
    size_t r1 = (size_t)(b*MAXKP + rk[1]) * KTOT + tid;
    g_Xh[r0] = h0;
    g_Xl[r0] = __float2bfloat16(v0 - __bfloat162float(h0));
    g_Xh[r1] = h1v;
    g_Xl[r1] = __float2bfloat16(v1 - __bfloat162float(h1v));
}

// ---------------- tensor-core GEMM via mma.sync (bf16 hi/lo, fp32 acc) ----------------
#define BM 64
#define BN 64
#define BK 32
#define ASTR 48

__device__ __forceinline__ void mma16816(float c[4],
    uint32_t a0, uint32_t a1, uint32_t a2, uint32_t a3,
    uint32_t b0, uint32_t b1)
{
    asm volatile(
        "mma.sync.aligned.m16n8k16.row.col.f32.bf16.bf16.f32 "
        "{%0,%1,%2,%3}, {%4,%5,%6,%7}, {%8,%9}, {%0,%1,%2,%3};"
        : "+f"(c[0]), "+f"(c[1]), "+f"(c[2]), "+f"(c[3])
        : "r"(a0), "r"(a1), "r"(a2), "r"(a3), "r"(b0), "r"(b1));
}

__global__ void __launch_bounds__(256) k_gemm_mma(float* __restrict__ outDesc)
{
    __shared__ __nv_bfloat16 sAh[BM][ASTR], sAl[BM][ASTR];
    __shared__ __nv_bfloat16 sBh[BN][ASTR], sBl[BN][ASTR];

    int tid = threadIdx.x;
    int wid = tid >> 5, lane = tid & 31;
    int grp = lane >> 2, qid = lane & 3;
    int wm = wid & 1;
    int wn = wid >> 1;
    int o0 = blockIdx.y * BM;
    int n0 = blockIdx.x * BN;

    float c[2][2][4];
    #pragma unroll
    for (int mt = 0; mt < 2; mt++)
        #pragma unroll
        for (int nt = 0; nt < 2; nt++)
            #pragma unroll
            for (int r = 0; r < 4; r++) c[mt][nt][r] = 0.f;

    for (int k0 = 0; k0 < KTOT; k0 += BK) {
        {
            int row = tid >> 2, j = tid & 3;
            *(uint4*)&sAh[row][j*8] = *(const uint4*)(g_Mh + (o0+row)*KTOT + k0 + j*8);
            *(uint4*)&sAl[row][j*8] = *(const uint4*)(g_Ml + (o0+row)*KTOT + k0 + j*8);
            size_t gi = (size_t)(n0+row)*KTOT + k0 + j*8;
            *(uint4*)&sBh[row][j*8] = *(const uint4*)(g_Xh + gi);
            *(uint4*)&sBl[row][j*8] = *(const uint4*)(g_Xl + gi);
        }
        __syncthreads();

        #pragma unroll
        for (int ks = 0; ks < 2; ks++) {
            int kb = ks*16 + qid*2;
            uint32_t ah[2][4], al[2][4];
            #pragma unroll
            for (int mt = 0; mt < 2; mt++) {
                int r0 = wm*32 + mt*16 + grp;
                ah[mt][0] = *(const uint32_t*)&sAh[r0  ][kb  ];
                ah[mt][1] = *(const uint32_t*)&sAh[r0+8][kb  ];
                ah[mt][2] = *(const uint32_t*)&sAh[r0  ][kb+8];
                ah[mt][3] = *(const uint32_t*)&sAh[r0+8][kb+8];
                al[mt][0] = *(const uint32_t*)&sAl[r0  ][kb  ];
                al[mt][1] = *(const uint32_t*)&sAl[r0+8][kb  ];
                al[mt][2] = *(const uint32_t*)&sAl[r0  ][kb+8];
                al[mt][3] = *(const uint32_t*)&sAl[r0+8][kb+8];
            }
            #pragma unroll
            for (int nt = 0; nt < 2; nt++) {
                int nr = wn*16 + nt*8 + grp;
                uint32_t bh0 = *(const uint32_t*)&sBh[nr][kb  ];
                uint32_t bh1 = *(const uint32_t*)&sBh[nr][kb+8];
                uint32_t bl0 = *(const uint32_t*)&sBl[nr][kb  ];
                uint32_t bl1 = *(const uint32_t*)&sBl[nr][kb+8];
                #pragma unroll
                for (int mt = 0; mt < 2; mt++) {
                    mma16816(c[mt][nt], ah[mt][0], ah[mt][1], ah[mt][2], ah[mt][3], bh0, bh1);
                    mma16816(c[mt][nt], ah[mt][0], ah[mt][1], ah[mt][2], ah[mt][3], bl0, bl1);
                    mma16816(c[mt][nt], al[mt][0], al[mt][1], al[mt][2], al[mt][3], bh0, bh1);
                }
            }
        }
        __syncthreads();
    }

    int b = n0 >> 10;
    int nin = n0 & 1023;
    #pragma unroll
    for (int mt = 0; mt < 2; mt++) {
        int o = o0 + wm*32 + mt*16 + grp;
        float bias0 = g_bias[o];
        float bias8 = g_bias[o+8];
        float* row0 = outDesc + (size_t)(b*256 + o    )*MAXKP + nin;
        float* row8 = outDesc + (size_t)(b*256 + o + 8)*MAXKP + nin;
        #pragma unroll
        for (int nt = 0; nt < 2; nt++) {
            int nc = wn*16 + nt*8 + qid*2;
            *(float2*)(row0 + nc) = make_float2(c[mt][nt][0] + bias0, c[mt][nt][1] + bias0);
            *(float2*)(row8 + nc) = make_float2(c[mt][nt][2] + bias8, c[mt][nt][3] + bias8);
        }
    }
}

// ---------------- launch ----------------
#define SEL_SMEM ((CKCAP + SELCAP)*8 + NBUCK*4)   // 128KB

extern "C" void kernel_launch(void* const* d_in, const int* in_sizes, int n_in,
                              void* d_out, int out_size)
{
    const float* scores  = (const float*)d_in[0];
    const float* d1      = (const float*)d_in[1];
    const float* d2      = (const float*)d_in[2];
    const float* d3      = (const float*)d_in[3];
    const float* d4      = (const float*)d_in[4];
    const float* lin0_w  = (const float*)d_in[5];
    const float* lin0_b  = (const float*)d_in[6];
    const float* lin1_w  = (const float*)d_in[7];
    const float* lin1_b  = (const float*)d_in[8];
    const float* lin2_w  = (const float*)d_in[9];
    const float* lin2_b  = (const float*)d_in[10];
    const float* merge_w = (const float*)d_in[11];
    const float* merge_b = (const float*)d_in[12];

    float* out     = (float*)d_out;
    float* outKp   = out;
    float* outSc   = out + BB*MAXKP*2;
    float* outDesc = out + BB*MAXKP*2 + BB*MAXKP;

    cudaFuncSetAttribute(k_select, cudaFuncAttributeMaxDynamicSharedMemorySize, SEL_SMEM);

    dim3 tgridA(WW/TX, HH/TY, BB + 1);   // z==4: reset + weight fold layer
    dim3 tgridB(WW/TX, HH/TY, BB);

    k_nmsA<<<tgridA, 256>>>(scores, merge_w, lin0_w, lin1_w, lin2_w,
                            merge_b, lin0_b, lin1_b, lin2_b);
    k_nmsB<<<tgridB, 256>>>(scores);

    k_select<<<BB, 1024, SEL_SMEM>>>(outKp, outSc);
    k_sample<<<(BB*MAXKP)/2, 704>>>(d1, d2, d3, d4);
    k_gemm_mma<<<dim3((BB*MAXKP)/BN, 256/BM), 256>>>(outDesc);
}

// round 16
// speedup vs baseline: 1.1363x; 1.1363x over previous
#include <cuda_runtime.h>
#include <cuda_bf16.h>
#include <cstdint>
#include <math.h>

// ---------------- problem constants ----------------
#define BB 4
#define HH 480
#define WW 640
#define HWW (HH*WW)
#define BHW (BB*HWW)
#define RAD 4
#define THR 0.005f
#define MAXKP 1024
#define CAP 16384
#define NBUCK 4096
#define SELCAP 2048
#define CKCAP 12288
#define KTOT 704

#define C1 64
#define H1 240
#define W1 320
#define C2 128
#define H2 120
#define W2 160
#define C3 256
#define H3 60
#define W3 80
#define C4 256
#define H4 30
#define W4 40

// NMS tiles
#define TX 64
#define TY 16

// ---------------- scratch ----------------
__device__ unsigned char      g_maxmask[BHW];
__device__ unsigned long long g_cand[BB*CAP];
__device__ int                g_count[BB];
__device__ int                g_hist[BB*NBUCK];
__device__ int                g_selidx[BB*MAXKP];
__device__ __align__(16) __nv_bfloat16 g_Xh[(size_t)BB*MAXKP*KTOT];
__device__ __align__(16) __nv_bfloat16 g_Xl[(size_t)BB*MAXKP*KTOT];
__device__ __align__(16) __nv_bfloat16 g_Mh[256*KTOT];
__device__ __align__(16) __nv_bfloat16 g_Ml[256*KTOT];
__device__ float              g_bias[256];

// ---------------- fused NMS A (+ reset/fold layer at blockIdx.z==4) ----------------
__global__ void __launch_bounds__(256) k_nmsA(const float* __restrict__ sc,
    const float* __restrict__ mw,
    const float* __restrict__ l0w, const float* __restrict__ l1w,
    const float* __restrict__ l2w,
    const float* __restrict__ mb,
    const float* __restrict__ l0b, const float* __restrict__ l1b,
    const float* __restrict__ l2b)
{
    int tid = threadIdx.x;

    if (blockIdx.z == 4) {
        int bid = blockIdx.y*10 + blockIdx.x;            // 0..299
        if (bid < 64) {
            g_hist[bid*256 + tid] = 0;
            if (bid == 0 && tid < BB) g_count[tid] = 0;
        }
        if (bid == 0) {
            int o = tid;
            const float* mrow = mw + o*KTOT;
            float acc = mb[o];
            for (int j = 0; j < 64;  j++) acc += mrow[j]       * l2b[j];
            for (int j = 0; j < 128; j++) acc += mrow[64 + j]  * l1b[j];
            for (int j = 0; j < 256; j++) acc += mrow[448 + j] * l0b[j];
            g_bias[o] = acc;
        }
        int gid = bid*256 + tid;
        for (int t = gid; t < 256*KTOT; t += 300*256) {
            int o = t / KTOT, i = t % KTOT;
            const float* mrow = mw + o*KTOT;
            float acc = 0.f;
            if (i < 64) {
                for (int j = 0; j < 64; j++)  acc += mrow[j]       * l2w[j*64  + i];
            } else if (i < 192) {
                int ii = i - 64;
                for (int j = 0; j < 128; j++) acc += mrow[64 + j]  * l1w[j*128 + ii];
            } else if (i < 448) {
                acc = mrow[i];
            } else {
                int ii = i - 448;
                for (int j = 0; j < 256; j++) acc += mrow[448 + j] * l0w[j*256 + ii];
            }
            __nv_bfloat16 hi = __float2bfloat16(acc);
            g_Mh[t] = hi;
            g_Ml[t] = __float2bfloat16(acc - __bfloat162float(hi));
        }
        return;
    }

    __shared__ float         s0[40][89];
    __shared__ float         h1[40][81];
    __shared__ unsigned char m0[32][84];
    __shared__ unsigned char hor1[32][76];
    __shared__ unsigned char sup[24][76];
    __shared__ float         ss1[24][76];
    __shared__ float         h2[24][68];

    int b = blockIdx.z;
    int x0 = blockIdx.x*TX, y0 = blockIdx.y*TY;
    const float* S = sc + b*HWW;
    int tx = tid & 63, ty = tid >> 6;

    for (int ly = ty; ly < 40; ly += 4) {
        #pragma unroll
        for (int lxb = 0; lxb < 2; lxb++) {
            int lx = lxb*64 + tx;
            if (lx < 88) {
                int gx = x0 + lx - 12, gy = y0 + ly - 12;
                s0[ly][lx] = (gx >= 0 && gx < WW && gy >= 0 && gy < HH)
                           ? S[gy*WW + gx] : -INFINITY;
            }
        }
    }
    __syncthreads();
    for (int ly = ty; ly < 40; ly += 4) {
        #pragma unroll
        for (int lxb = 0; lxb < 2; lxb++) {
            int lx = lxb*64 + tx;
            if (lx < 80) {
                float m = s0[ly][lx];
                #pragma unroll
                for (int d = 1; d < 9; d++) m = fmaxf(m, s0[ly][lx+d]);
                h1[ly][lx] = m;
            }
        }
    }
    __syncthreads();
    for (int ly = ty; ly < 32; ly += 4) {
        #pragma unroll
        for (int lxb = 0; lxb < 2; lxb++) {
            int lx = lxb*64 + tx;
            if (lx < 80) {
                float m = h1[ly][lx];
                #pragma unroll
                for (int d = 1; d < 9; d++) m = fmaxf(m, h1[ly+d][lx]);
                int gx = x0 + lx - 8, gy = y0 + ly - 8;
                bool in = (gx >= 0 && gx < WW && gy >= 0 && gy < HH);
                m0[ly][lx] = (in && s0[ly+4][lx+4] == m) ? 1 : 0;
            }
        }
    }
    __syncthreads();
    for (int ly = ty; ly < 32; ly += 4) {
        #pragma unroll
        for (int lxb = 0; lxb < 2; lxb++) {
            int lx = lxb*64 + tx;
            if (lx < 72) {
                unsigned char u = m0[ly][lx];
                #pragma unroll
                for (int d = 1; d < 9; d++) u |= m0[ly][lx+d];
                hor1[ly][lx] = u;
            }
        }
    }
    __syncthreads();
    for (int ly = ty; ly < 24; ly += 4) {
        #pragma unroll
        for (int lxb = 0; lxb < 2; lxb++) {
            int lx = lxb*64 + tx;
            if (lx < 72) {
                unsigned char u = hor1[ly][lx];
                #pragma unroll
                for (int d = 1; d < 9; d++) u |= hor1[ly+d][lx];
                sup[ly][lx] = u;
                int gx = x0 + lx - 4, gy = y0 + ly - 4;
                float v = -INFINITY;
                if (gx >= 0 && gx < WW && gy >= 0 && gy < HH)
                    v = u ? 0.0f : s0[ly+8][lx+8];
                ss1[ly][lx] = v;
            }
        }
    }
    __syncthreads();
    for (int ly = ty; ly < 24; ly += 4) {
        int lx = tx;
        float m = ss1[ly][lx];
        #pragma unroll
        for (int d = 1; d < 9; d++) m = fmaxf(m, ss1[ly][lx+d]);
        h2[ly][lx] = m;
    }
    __syncthreads();
    for (int ly = ty; ly < 16; ly += 4) {
        int lx = tx;
        float m = h2[ly][lx];
        #pragma unroll
        for (int d = 1; d < 9; d++) m = fmaxf(m, h2[ly+d][lx]);
        unsigned char sp = sup[ly+4][lx+4];
        float ssc = ss1[ly+4][lx+4];
        unsigned char newm = ((ssc == m) && !sp) ? 1 : 0;
        int gx = x0 + lx, gy = y0 + ly;
        g_maxmask[b*HWW + gy*WW + gx] = m0[ly+8][lx+8] | newm;
    }
}

// ---------------- fused NMS B: iteration 2 + candidate emission ----------------
__global__ void __launch_bounds__(256) k_nmsB(const float* __restrict__ sc)
{
    __shared__ unsigned char mm[TY+16][TX+16+4];
    __shared__ unsigned char hor[TY+16][TX+8+4];
    __shared__ unsigned char sup[TY+8][TX+8+4];
    __shared__ float         sfl[TY+8][TX+8+4];
    __shared__ float         hmx[TY+8][TX+4];
    int b = blockIdx.z;
    int x0 = blockIdx.x*TX, y0 = blockIdx.y*TY;
    const float* S = sc + b*HWW;
    const unsigned char* SM = g_maxmask + b*HWW;

    for (int e = threadIdx.x; e < (TY+16)*(TX+16); e += 256) {
        int ly = e / (TX+16), lx = e % (TX+16);
        int gx = x0 + lx - 8, gy = y0 + ly - 8;
        unsigned char v = 0;
        if (gx >= 0 && gx < WW && gy >= 0 && gy < HH) v = SM[gy*WW + gx];
        mm[ly][lx] = v;
    }
    __syncthreads();
    for (int e = threadIdx.x; e < (TY+16)*(TX+8); e += 256) {
        int ly = e / (TX+8), lx = e % (TX+8);
        unsigned char u = mm[ly][lx];
        #pragma unroll
        for (int d = 1; d < 9; d++) u |= mm[ly][lx+d];
        hor[ly][lx] = u;
    }
    __syncthreads();
    for (int e = threadIdx.x; e < (TY+8)*(TX+8); e += 256) {
        int ly = e / (TX+8), lx = e % (TX+8);
        unsigned char u = hor[ly][lx];
        #pragma unroll
        for (int d = 1; d < 9; d++) u |= hor[ly+d][lx];
        sup[ly][lx] = u;
        int gx = x0 + lx - 4, gy = y0 + ly - 4;
        float v = -INFINITY;
        if (gx >= 0 && gx < WW && gy >= 0 && gy < HH) v = u ? 0.0f : S[gy*WW + gx];
        sfl[ly][lx] = v;
    }
    __syncthreads();
    for (int e = threadIdx.x; e < (TY+8)*TX; e += 256) {
        int ly = e / TX, lx = e % TX;
        float m = sfl[ly][lx];
        #pragma unroll
        for (int d = 1; d < 9; d++) m = fmaxf(m, sfl[ly][lx+d]);
        hmx[ly][lx] = m;
    }
    __syncthreads();
    for (int e = threadIdx.x; e < TY*TX; e += 256) {
        int ly = e / TX, lx = e % TX;
        float m = hmx[ly][lx];
        #pragma unroll
        for (int d = 1; d < 9; d++) m = fmaxf(m, hmx[ly+d][lx]);
        unsigned char sp = sup[ly+4][lx+4];
        float ss = sfl[ly+4][lx+4];
        unsigned char newm = ((ss == m) && !sp) ? 1 : 0;
        int gx = x0 + lx, gy = y0 + ly;
        unsigned char maskv = mm[ly+8][lx+8] | newm;
        if (maskv && gx >= RAD && gx < WW-RAD && gy >= RAD && gy < HH-RAD) {
            float sv = S[gy*WW + gx];
            if (sv > THR) {
                unsigned sb = __float_as_uint(sv);
                int local = gy*WW + gx;
                int p = atomicAdd(&g_count[b], 1);
                if (p < CAP)
                    g_cand[b*CAP + p] = (((unsigned long long)sb) << 32)
                                      | (unsigned long long)(0xFFFFFFFFu - (unsigned)local);
                atomicAdd(&g_hist[b*NBUCK + (sb >> 20)], 1);
            }
        }
    }
}

// ---------------- warp-shuffle suffix scan over 1024 threads ----------------
__device__ __forceinline__ int suffix_scan1024(int v, int tid, int* warptot)
{
    int lane = tid & 31, wid = tid >> 5;
    int s = v;
    #pragma unroll
    for (int o = 1; o < 32; o <<= 1) {
        int t = __shfl_down_sync(0xFFFFFFFFu, s, o);
        if (lane + o < 32) s += t;
    }
    if (lane == 0) warptot[wid] = s;
    __syncthreads();
    if (wid == 0) {
        int wv = warptot[lane];
        int ws = wv;
        #pragma unroll
        for (int o = 1; o < 32; o <<= 1) {
            int t = __shfl_down_sync(0xFFFFFFFFu, ws, o);
            if (lane + o < 32) ws += t;
        }
        warptot[lane] = ws - wv;
    }
    __syncthreads();
    return s + warptot[wid];
}

// ---------------- single-global-pass radix-select + rank scatter ----------------
__global__ void __launch_bounds__(1024) k_select(float* __restrict__ outKp,
                                                 float* __restrict__ outSc)
{
    extern __shared__ unsigned long long dyns[];
    unsigned long long* ckey = dyns;
    unsigned long long* sel  = dyns + CKCAP;
    int* hist2 = (int*)(dyns + CKCAP + SELCAP);
    __shared__ int warptot[32];
    __shared__ int s_T, s_T2, s_m, s_nhi, s_msel;

    int b = blockIdx.x;
    int tid = threadIdx.x;
    int cnt = g_count[b];
    if (cnt > CKCAP) cnt = CKCAP;

    int c0 = g_hist[b*NBUCK + tid*4 + 0];
    int c1 = g_hist[b*NBUCK + tid*4 + 1];
    int c2 = g_hist[b*NBUCK + tid*4 + 2];
    int c3 = g_hist[b*NBUCK + tid*4 + 3];
    if (tid == 0) { s_T = 0; s_T2 = 0; s_m = 0; s_nhi = 0; }
    hist2[tid] = 0; hist2[tid+1024] = 0; hist2[tid+2048] = 0; hist2[tid+3072] = 0;
    __syncthreads();
    int suf = suffix_scan1024(c0 + c1 + c2 + c3, tid, warptot);
    {
        int nx = suf - (c0 + c1 + c2 + c3);
        int C3v = nx + c3, C2v = C3v + c2, C1v = C2v + c1, C0v = C1v + c0;
        if (C0v >= MAXKP && C1v < MAXKP) s_T = tid*4 + 0;
        if (C1v >= MAXKP && C2v < MAXKP) s_T = tid*4 + 1;
        if (C2v >= MAXKP && C3v < MAXKP) s_T = tid*4 + 2;
        if (C3v >= MAXKP && nx  < MAXKP) s_T = tid*4 + 3;
    }
    __syncthreads();
    int Tstar = s_T;

    for (int t = tid; t < cnt; t += 1024) {
        unsigned long long key = g_cand[b*CAP + t];
        ckey[t] = key;
        int bucket = (int)(key >> 52);
        if (bucket > Tstar)        atomicAdd(&s_nhi, 1);
        else if (bucket == Tstar)  atomicAdd(&hist2[(int)((key >> 40) & 0xFFF)], 1);
    }
    __syncthreads();
    int q0 = hist2[tid*4 + 0], q1 = hist2[tid*4 + 1];
    int q2 = hist2[tid*4 + 2], q3 = hist2[tid*4 + 3];
    int nhi = s_nhi;
    __syncthreads();
    int suf2 = suffix_scan1024(q0 + q1 + q2 + q3, tid, warptot);
    {
        int nx = suf2 - (q0 + q1 + q2 + q3);
        int D3 = nx + q3, D2 = D3 + q2, D1 = D2 + q1, D0 = D1 + q0;
        if (nhi + D0 >= MAXKP && nhi + D1 < MAXKP) { s_T2 = tid*4 + 0; s_msel = nhi + D0; }
        if (nhi + D1 >= MAXKP && nhi + D2 < MAXKP) { s_T2 = tid*4 + 1; s_msel = nhi + D1; }
        if (nhi + D2 >= MAXKP && nhi + D3 < MAXKP) { s_T2 = tid*4 + 2; s_msel = nhi + D2; }
        if (nhi + D3 >= MAXKP && nhi + nx < MAXKP) { s_T2 = tid*4 + 3; s_msel = nhi + D3; }
        if (tid == 0 && nhi + suf2 < MAXKP) s_msel = nhi + suf2;
    }
    __syncthreads();
    int T2 = s_T2;

    for (int t = tid; t < cnt; t += 1024) {
        unsigned long long key = ckey[t];
        int bucket = (int)(key >> 52);
        int sub    = (int)((key >> 40) & 0xFFF);
        if (bucket > Tstar || (bucket == Tstar && sub >= T2)) {
            int p = atomicAdd(&s_m, 1);
            if (p < SELCAP) sel[p] = key;
        }
    }
    __syncthreads();
    int m = s_m; if (m > SELCAP) m = SELCAP;

    for (int t = tid; t < m; t += 1024) {
        unsigned long long key = sel[t];
        int rank = 0;
        int j = 0;
        for (; j + 4 <= m; j += 4) {
            rank += (sel[j]   > key);
            rank += (sel[j+1] > key);
            rank += (sel[j+2] > key);
            rank += (sel[j+3] > key);
        }
        for (; j < m; j++) rank += (sel[j] > key);
        if (rank < MAXKP) {
            float s = __uint_as_float((unsigned)(key >> 32));
            int idx = (int)(0xFFFFFFFFu - (unsigned)(key & 0xFFFFFFFFu));
            outKp[(b*MAXKP + rank)*2 + 0] = (float)(idx % WW);
            outKp[(b*MAXKP + rank)*2 + 1] = (float)(idx / WW);
            outSc[b*MAXKP + rank] = s;
            g_selidx[b*MAXKP + rank] = idx;
        }
    }
    for (int p = m + tid; p < MAXKP; p += 1024) {
        int idx = p - m;
        outKp[(b*MAXKP + p)*2 + 0] = (float)(idx % WW);
        outKp[(b*MAXKP + p)*2 + 1] = (float)(idx / WW);
        outSc[b*MAXKP + p] = -1.0f;
        g_selidx[b*MAXKP + p] = idx;
    }
}

// ---------------- descriptor sampling: tap-major, 4 keypoints/block ----------------
__global__ void __launch_bounds__(704) k_sample(
    const float* __restrict__ d1, const float* __restrict__ d2,
    const float* __restrict__ d3, const float* __restrict__ d4)
{
    __shared__ float xs[4][KTOT];
    __shared__ float wsum[4][22];
    int n0 = blockIdx.x * 4;
    int b = n0 >> 10;
    int tid = threadIdx.x;

    const float* dptr; int h, w, sfac, warp0, nw, choff;
    if (tid < 64)       { dptr = d1 + (size_t)b*C1*H1*W1; h=H1; w=W1; sfac=2;  warp0=0;  nw=2; choff=0;   }
    else if (tid < 192) { dptr = d2 + (size_t)b*C2*H2*W2; h=H2; w=W2; sfac=4;  warp0=2;  nw=4; choff=64;  }
    else if (tid < 448) { dptr = d3 + (size_t)b*C3*H3*W3; h=H3; w=W3; sfac=8;  warp0=6;  nw=8; choff=192; }
    else                { dptr = d4 + (size_t)b*C4*H4*W4; h=H4; w=W4; sfac=16; warp0=14; nw=8; choff=448; }

    int lane = tid & 31, wid = tid >> 5;
    int tap = lane & 3, chl = lane >> 2;
    int warp_in_group = wid - warp0;

    int toff[4]; float wt[4];
    #pragma unroll
    for (int k = 0; k < 4; k++) {
        int idx = g_selidx[n0 + k];
        float kx = (float)(idx % WW), ky = (float)(idx / WW);
        float kxs = kx - (float)sfac * 0.5f + 0.5f;
        float kys = ky - (float)sfac * 0.5f + 0.5f;
        float gx = kxs / (float)(w * sfac - 1) * 2.0f - 1.0f;
        float gy = kys / (float)(h * sfac - 1) * 2.0f - 1.0f;
        float x = (gx + 1.0f) * 0.5f * (float)(w - 1);
        float y = (gy + 1.0f) * 0.5f * (float)(h - 1);
        float x0f = floorf(x), y0f = floorf(y);
        float wx1 = x - x0f, wy1 = y - y0f;
        float wx0 = 1.0f - wx1, wy0 = 1.0f - wy1;
        int x0 = (int)x0f, y0 = (int)y0f;
        int x1 = x0 + 1,  y1 = y0 + 1;
        int xc0 = min(max(x0, 0), w-1), xc1 = min(max(x1, 0), w-1);
        int yc0 = min(max(y0, 0), h-1), yc1 = min(max(y1, 0), h-1);
        float f00 = (x0 >= 0 && x0 < w && y0 >= 0 && y0 < h) ? 1.f : 0.f;
        float f10 = (x1 >= 0 && x1 < w && y0 >= 0 && y0 < h) ? 1.f : 0.f;
        float f01 = (x0 >= 0 && x0 < w && y1 >= 0 && y1 < h) ? 1.f : 0.f;
        float f11 = (x1 >= 0 && x1 < w && y1 >= 0 && y1 < h) ? 1.f : 0.f;
        float w00 = (wx0*wy0)*f00, w10 = (wx1*wy0)*f10;
        float w01 = (wx0*wy1)*f01, w11 = (wx1*wy1)*f11;
        int ytap = (tap & 2) ? yc1 : yc0;
        int xtap = (tap & 1) ? xc1 : xc0;
        wt[k]  = (tap == 0) ? w00 : (tap == 1) ? w10 : (tap == 2) ? w01 : w11;
        toff[k] = ytap*w + xtap;
    }

    // gather: 4 iterations x 8 channels x 4 keypoints (16 LDGs in flight)
    #pragma unroll
    for (int i = 0; i < 4; i++) {
        int chg = warp_in_group*32 + i*8 + chl;
        const float* base = dptr + (size_t)chg*h*w;
        float v0 = __ldg(base + toff[0]) * wt[0];
        float v1 = __ldg(base + toff[1]) * wt[1];
        float v2 = __ldg(base + toff[2]) * wt[2];
        float v3 = __ldg(base + toff[3]) * wt[3];
        v0 += __shfl_xor_sync(0xFFFFFFFFu, v0, 1);
        v1 += __shfl_xor_sync(0xFFFFFFFFu, v1, 1);
        v2 += __shfl_xor_sync(0xFFFFFFFFu, v2, 1);
        v3 += __shfl_xor_sync(0xFFFFFFFFu, v3, 1);
        v0 += __shfl_xor_sync(0xFFFFFFFFu, v0, 2);
        v1 += __shfl_xor_sync(0xFFFFFFFFu, v1, 2);
        v2 += __shfl_xor_sync(0xFFFFFFFFu, v2, 2);
        v3 += __shfl_xor_sync(0xFFFFFFFFu, v3, 2);
        if (tap == 0) {
            xs[0][choff + chg] = v0;
            xs[1][choff + chg] = v1;
            xs[2][choff + chg] = v2;
            xs[3][choff + chg] = v3;
        }
    }
    __syncthreads();

    // norm + write (tid == channel index), all four keypoints
    float rv[4], sq[4];
    #pragma unroll
    for (int k = 0; k < 4; k++) { rv[k] = xs[k][tid]; sq[k] = rv[k]*rv[k]; }
    #pragma unroll
    for (int o = 16; o > 0; o >>= 1) {
        #pragma unroll
        for (int k = 0; k < 4; k++) sq[k] += __shfl_xor_sync(0xFFFFFFFFu, sq[k], o);
    }
    if (lane == 0) {
        #pragma unroll
        for (int k = 0; k < 4; k++) wsum[k][wid] = sq[k];
    }
    __syncthreads();
    #pragma unroll
    for (int k = 0; k < 4; k++) {
        float tot = 0.f;
        for (int i = 0; i < nw; i++) tot += wsum[k][warp0 + i];
        float v = rv[k] / fmaxf(sqrtf(tot), 1e-12f);
        __nv_bfloat16 hi = __float2bfloat16(v);
        size_t r = (size_t)(n0 + k) * KTOT + tid;
        g_Xh[r] = hi;
        g_Xl[r] = __float2bfloat16(v - __bfloat162float(hi));
    }
}

// ---------------- tensor-core GEMM via mma.sync (bf16 hi/lo, fp32 acc) ----------------
#define BM 64
#define BN 64
#define BK 32
#define ASTR 48

__device__ __forceinline__ void mma16816(float c[4],
    uint32_t a0, uint32_t a1, uint32_t a2, uint32_t a3,
    uint32_t b0, uint32_t b1)
{
    asm volatile(
        "mma.sync.aligned.m16n8k16.row.col.f32.bf16.bf16.f32 "
        "{%0,%1,%2,%3}, {%4,%5,%6,%7}, {%8,%9}, {%0,%1,%2,%3};"
        : "+f"(c[0]), "+f"(c[1]), "+f"(c[2]), "+f"(c[3])
        : "r"(a0), "r"(a1), "r"(a2), "r"(a3), "r"(b0), "r"(b1));
}

__global__ void __launch_bounds__(256) k_gemm_mma(float* __restrict__ outDesc)
{
    __shared__ __nv_bfloat16 sAh[BM][ASTR], sAl[BM][ASTR];
    __shared__ __nv_bfloat16 sBh[BN][ASTR], sBl[BN][ASTR];

    int tid = threadIdx.x;
    int wid = tid >> 5, lane = tid & 31;
    int grp = lane >> 2, qid = lane & 3;
    int wm = wid & 1;
    int wn = wid >> 1;
    int o0 = blockIdx.y * BM;
    int n0 = blockIdx.x * BN;

    float c[2][2][4];
    #pragma unroll
    for (int mt = 0; mt < 2; mt++)
        #pragma unroll
        for (int nt = 0; nt < 2; nt++)
            #pragma unroll
            for (int r = 0; r < 4; r++) c[mt][nt][r] = 0.f;

    for (int k0 = 0; k0 < KTOT; k0 += BK) {
        {
            int row = tid >> 2, j = tid & 3;
            *(uint4*)&sAh[row][j*8] = *(const uint4*)(g_Mh + (o0+row)*KTOT + k0 + j*8);
            *(uint4*)&sAl[row][j*8] = *(const uint4*)(g_Ml + (o0+row)*KTOT + k0 + j*8);
            size_t gi = (size_t)(n0+row)*KTOT + k0 + j*8;
            *(uint4*)&sBh[row][j*8] = *(const uint4*)(g_Xh + gi);
            *(uint4*)&sBl[row][j*8] = *(const uint4*)(g_Xl + gi);
        }
        __syncthreads();

        #pragma unroll
        for (int ks = 0; ks < 2; ks++) {
            int kb = ks*16 + qid*2;
            uint32_t ah[2][4], al[2][4];
            #pragma unroll
            for (int mt = 0; mt < 2; mt++) {
                int r0 = wm*32 + mt*16 + grp;
                ah[mt][0] = *(const uint32_t*)&sAh[r0  ][kb  ];
                ah[mt][1] = *(const uint32_t*)&sAh[r0+8][kb  ];
                ah[mt][2] = *(const uint32_t*)&sAh[r0  ][kb+8];
                ah[mt][3] = *(const uint32_t*)&sAh[r0+8][kb+8];
                al[mt][0] = *(const uint32_t*)&sAl[r0  ][kb  ];
                al[mt][1] = *(const uint32_t*)&sAl[r0+8][kb  ];
                al[mt][2] = *(const uint32_t*)&sAl[r0  ][kb+8];
                al[mt][3] = *(const uint32_t*)&sAl[r0+8][kb+8];
            }
            #pragma unroll
            for (int nt = 0; nt < 2; nt++) {
                int nr = wn*16 + nt*8 + grp;
                uint32_t bh0 = *(const uint32_t*)&sBh[nr][kb  ];
                uint32_t bh1 = *(const uint32_t*)&sBh[nr][kb+8];
                uint32_t bl0 = *(const uint32_t*)&sBl[nr][kb  ];
                uint32_t bl1 = *(const uint32_t*)&sBl[nr][kb+8];
                #pragma unroll
                for (int mt = 0; mt < 2; mt++) {
                    mma16816(c[mt][nt], ah[mt][0], ah[mt][1], ah[mt][2], ah[mt][3], bh0, bh1);
                    mma16816(c[mt][nt], ah[mt][0], ah[mt][1], ah[mt][2], ah[mt][3], bl0, bl1);
                    mma16816(c[mt][nt], al[mt][0], al[mt][1], al[mt][2], al[mt][3], bh0, bh1);
                }
            }
        }
        __syncthreads();
    }

    int b = n0 >> 10;
    int nin = n0 & 1023;
    #pragma unroll
    for (int mt = 0; mt < 2; mt++) {
        int o = o0 + wm*32 + mt*16 + grp;
        float bias0 = g_bias[o];
        float bias8 = g_bias[o+8];
        float* row0 = outDesc + (size_t)(b*256 + o    )*MAXKP + nin;
        float* row8 = outDesc + (size_t)(b*256 + o + 8)*MAXKP + nin;
        #pragma unroll
        for (int nt = 0; nt < 2; nt++) {
            int nc = wn*16 + nt*8 + qid*2;
            *(float2*)(row0 + nc) = make_float2(c[mt][nt][0] + bias0, c[mt][nt][1] + bias0);
            *(float2*)(row8 + nc) = make_float2(c[mt][nt][2] + bias8, c[mt][nt][3] + bias8);
        }
    }
}

// ---------------- launch ----------------
#define SEL_SMEM ((CKCAP + SELCAP)*8 + NBUCK*4)   // 128KB

extern "C" void kernel_launch(void* const* d_in, const int* in_sizes, int n_in,
                              void* d_out, int out_size)
{
    const float* scores  = (const float*)d_in[0];
    const float* d1      = (const float*)d_in[1];
    const float* d2      = (const float*)d_in[2];
    const float* d3      = (const float*)d_in[3];
    const float* d4      = (const float*)d_in[4];
    const float* lin0_w  = (const float*)d_in[5];
    const float* lin0_b  = (const float*)d_in[6];
    const float* lin1_w  = (const float*)d_in[7];
    const float* lin1_b  = (const float*)d_in[8];
    const float* lin2_w  = (const float*)d_in[9];
    const float* lin2_b  = (const float*)d_in[10];
    const float* merge_w = (const float*)d_in[11];
    const float* merge_b = (const float*)d_in[12];

    float* out     = (float*)d_out;
    float* outKp   = out;
    float* outSc   = out + BB*MAXKP*2;
    float* outDesc = out + BB*MAXKP*2 + BB*MAXKP;

    cudaFuncSetAttribute(k_select, cudaFuncAttributeMaxDynamicSharedMemorySize, SEL_SMEM);

    dim3 tgridA(WW/TX, HH/TY, BB + 1);   // z==4: reset + weight fold layer
    dim3 tgridB(WW/TX, HH/TY, BB);

    k_nmsA<<<tgridA, 256>>>(scores, merge_w, lin0_w, lin1_w, lin2_w,
                            merge_b, lin0_b, lin1_b, lin2_b);
    k_nmsB<<<tgridB, 256>>>(scores);

    k_select<<<BB, 1024, SEL_SMEM>>>(outKp, outSc);
    k_sample<<<(BB*MAXKP)/4, 704>>>(d1, d2, d3, d4);
    k_gemm_mma<<<dim3((BB*MAXKP)/BN, 256/BM), 256>>>(outDesc);
}